// round 6
// baseline (speedup 1.0000x reference)
#include <cuda_runtime.h>

#define LL   128
#define BSZ  2
#define EE   768
#define HH   12
#define EH   384              // E/2
#define BHH  24               // B*H

// ---------------- scratch (device globals; no allocation allowed) -----------
__device__ float g_nq[256 * EE];            // conv1d(query) output, (L,B,E)
__device__ float g_proj[256 * 4 * EH];      // [q | k | v | e] per row, (256,1536)
__device__ float g_dq[BHH * LL];
__device__ float g_dk[BHH * LL];
__device__ float g_de[LL * BHH];
__device__ float g_a[256 * EE];             // attention output in (L,B,E)
__device__ float g_y[256 * EE];             // deconv output

// ---------------- packed f32x2 helpers --------------------------------------
#define FMA2(d, a, b) asm("fma.rn.f32x2 %0, %1, %2, %3;" \
                          : "=l"(d) : "l"(a), "l"(b), "l"(d))
#define DUP2(d, s)    asm("mov.b64 %0, {%1, %1};" : "=l"(d) : "f"(s))
#define PACK2(d, lo, hi) asm("mov.b64 %0, {%1, %2};" : "=l"(d) : "f"(lo), "f"(hi))
#define UNPK(lo, hi, s) asm("mov.b64 {%0, %1}, %2;" : "=f"(lo), "=f"(hi) : "l"(s))

// ---------------- init: zero atomic-accumulation targets (2 kernels) --------
__global__ __launch_bounds__(256)
void init_a_kernel()
{
    const int idx = blockIdx.x * 256 + threadIdx.x;   // 98304 float4
    float4 z = {0.f, 0.f, 0.f, 0.f};
    if (idx < 49152) ((float4*)g_nq)[idx] = z;
    else             ((float4*)g_y)[idx - 49152] = z;
}
__global__ __launch_bounds__(256)
void init_b_kernel(float* __restrict__ out)
{
    const int idx = blockIdx.x * 256 + threadIdx.x;   // 147456 float4
    float4 z = {0.f, 0.f, 0.f, 0.f};
    if (idx < 49152) ((float4*)out)[idx] = z;
    else             ((float4*)g_proj)[idx - 49152] = z;
}

// ---------------- double-buffered f32x2 SGEMM, BK=32, K-split ----------------
// 256 threads, tile 64x32. acc rows-packed: acc[rp][c] over rows (ty*4+2rp, +1)
// MODE 0: nq   = conv(query)      M=256 N=768  K=1536  KSPLIT=4
// MODE 1: proj = [q|k|v|e]        M=256 N=1536 K=768   KSPLIT=2
// MODE 2: y    = deconv(a)        M=256 N=768  K=1536  KSPLIT=4
// MODE 3: out  = y @ out_w^T      M=256 N=768  K=768   KSPLIT=2
template<int MODE, int KSPLIT>
__global__ __launch_bounds__(256)
void gemm_kernel(const float* __restrict__ A0,
                 const float* __restrict__ W0,
                 const float* __restrict__ W1,
                 const float* __restrict__ W2,
                 const float* __restrict__ W3,
                 const float* __restrict__ bb0,
                 const float* __restrict__ bb1,
                 const float* __restrict__ bb2,
                 const float* __restrict__ bb3,
                 float* __restrict__ Cout)
{
    constexpr int BM = 64, BN = 32, BK = 32;
    constexpr int N  = (MODE == 1) ? 1536 : 768;
    constexpr int K  = (MODE == 0 || MODE == 2) ? 1536 : 768;
    constexpr int NT = K / KSPLIT / BK;
    constexpr int ASTR = BM + 4;   // 68: 16B-aligned rows for LDS.128
    constexpr int BSTR = BN + 2;   // 34: 8B-aligned rows for LDS.64

    __shared__ __align__(16) float As[2][BK][ASTR];
    __shared__ __align__(16) float Bs[2][BK][BSTR];

    const int bn   = blockIdx.x * BN;
    const int bm   = blockIdx.y * BM;
    const int koff = blockIdx.z * (K / KSPLIT);
    const int tid  = threadIdx.x;
    const int tx   = tid & 15;     // 16 col-groups * 2 cols
    const int ty   = tid >> 4;     // 16 row-groups * 4 rows

    // loader coordinates
    const int aKK = tid & 31;            // A: k within tile
    const int aTY = tid >> 5;            // A: row fragment 0..7
    const int bKK = tid & 31;            // B (modes 0,1,3): k
    const int bTY = tid >> 5;            // o fragment 0..7
    const int bO2 = tid & 31;            // B (mode 2): o
    const int bK2 = tid >> 5;            // k fragment 0..7

    float ar[8], br[4];

    auto loadA = [&](int t) {
        const int k = koff + t * BK + aKK;
        #pragma unroll
        for (int i = 0; i < 8; i++) {
            const int row = bm + i * 8 + aTY;
            float v;
            if (MODE == 0) {
                if (k < EE) v = (row >= BSZ) ? A0[(row - BSZ) * EE + k] : 0.f;
                else        v = A0[row * EE + (k - EE)];
            } else if (MODE == 1) {
                const float* Ap = (bn >= 3 * EH) ? A0 : g_nq;
                v = Ap[row * EE + k];
            } else if (MODE == 2) {
                if (k < EE) v = g_a[row * EE + k];
                else        v = (row >= BSZ) ? g_a[(row - BSZ) * EE + (k - EE)] : 0.f;
            } else {
                v = g_y[row * EE + k];
            }
            ar[i] = v;
        }
    };

    auto loadB = [&](int t) {
        if (MODE == 2) {
            const int o = bn + bO2;
            #pragma unroll
            for (int i = 0; i < 4; i++) {
                const int k = koff + t * BK + i * 8 + bK2;
                br[i] = (k < EE) ? W0[(k * EE + o) * 2]
                                 : W0[((k - EE) * EE + o) * 2 + 1];
            }
        } else {
            const int k = koff + t * BK + bKK;
            #pragma unroll
            for (int i = 0; i < 4; i++) {
                const int o = bn + i * 8 + bTY;
                float v;
                if (MODE == 0) {
                    v = (k < EE) ? W0[(o * EE + k) * 2]
                                 : W0[(o * EE + (k - EE)) * 2 + 1];
                } else if (MODE == 1) {
                    if (o < EH)          v = W0[o * EE + k];
                    else if (o < 2 * EH) v = W1[(o - EH) * EE + k];
                    else if (o < 3 * EH) v = W2[(o - 2 * EH) * EE + k];
                    else                 v = W3[(o - 3 * EH) * EE + k];
                } else {
                    v = W0[o * EE + k];
                }
                br[i] = v;
            }
        }
    };

    auto storeTiles = [&](int nb) {
        #pragma unroll
        for (int i = 0; i < 8; i++) As[nb][aKK][i * 8 + aTY] = ar[i];
        if (MODE == 2) {
            #pragma unroll
            for (int i = 0; i < 4; i++) Bs[nb][i * 8 + bK2][bO2] = br[i];
        } else {
            #pragma unroll
            for (int i = 0; i < 4; i++) Bs[nb][bKK][i * 8 + bTY] = br[i];
        }
    };

    unsigned long long acc[2][2] = {};

    loadA(0); loadB(0);
    storeTiles(0);
    __syncthreads();

    int buf = 0;
    for (int t = 0; t < NT; t++) {
        if (t + 1 < NT) { loadA(t + 1); loadB(t + 1); }

        #pragma unroll
        for (int kk = 0; kk < BK; kk++) {
            const ulonglong2 av = *(const ulonglong2*)&As[buf][kk][ty * 4];
            const float2 b01 = *(const float2*)&Bs[buf][kk][tx * 2];
            unsigned long long bd0, bd1;
            DUP2(bd0, b01.x); DUP2(bd1, b01.y);
            FMA2(acc[0][0], av.x, bd0);
            FMA2(acc[0][1], av.x, bd1);
            FMA2(acc[1][0], av.y, bd0);
            FMA2(acc[1][1], av.y, bd1);
        }

        if (t + 1 < NT) {
            storeTiles(buf ^ 1);
            __syncthreads();
            buf ^= 1;
        }
    }

    // ---- epilogue: atomic accumulate (+bias on z==0) ---------------------------
    float* C = (MODE == 0) ? g_nq : (MODE == 1) ? g_proj
             : (MODE == 2) ? g_y  : Cout;
    const int oB = bn + tx * 2;
    float bias0, bias1;
    if (MODE == 1) {
        const int seg = oB / EH;                       // 0..3 (EH not pow2!)
        const float* bp = (seg == 0) ? bb0 : (seg == 1) ? bb1
                        : (seg == 2) ? bb2 : bb3;
        const int ob = oB - seg * EH;
        bias0 = bp[ob]; bias1 = bp[ob + 1];
    } else {
        bias0 = bb0[oB]; bias1 = bb0[oB + 1];
    }
    if (blockIdx.z != 0) { bias0 = 0.f; bias1 = 0.f; }

    #pragma unroll
    for (int rp = 0; rp < 2; rp++) {
        float c0lo, c0hi, c1lo, c1hi;
        UNPK(c0lo, c0hi, acc[rp][0]);
        UNPK(c1lo, c1hi, acc[rp][1]);
        const int r0 = bm + ty * 4 + rp * 2;
        atomicAdd(&C[r0 * N + oB],           c0lo + bias0);
        atomicAdd(&C[r0 * N + oB + 1],       c1lo + bias1);
        atomicAdd(&C[(r0 + 1) * N + oB],     c0hi + bias0);
        atomicAdd(&C[(r0 + 1) * N + oB + 1], c1hi + bias1);
    }
}

// ---------------- dq / dk / de precompute (9216 length-64 dots) -------------
__global__ __launch_bounds__(256)
void dots_kernel(const float* __restrict__ entity,
                 const float* __restrict__ attn_w)
{
    int w    = (blockIdx.x * blockDim.x + threadIdx.x) >> 5;
    int lane = threadIdx.x & 31;
    if (w >= 3 * BHH * LL) return;
    int which = w / (BHH * LL);
    int idx   = w % (BHH * LL);
    float v;
    if (which < 2) {
        int m = idx >> 7, x = idx & 127;
        int b = m / HH, h = m % HH;
        int row = x * BSZ + b;
        int base = (h < 6) ? (row * 1536 + which * EH + h * 64)
                           : (row * 1536 + 3 * EH + (h - 6) * 64);
        const float* wv = attn_w + which * 64;
        v = g_proj[base + lane] * wv[lane] + g_proj[base + lane + 32] * wv[lane + 32];
    } else {
        int i = idx / BHH, s = idx % BHH;
        int b = s / HH, h = s % HH;
        int base = (i * BSZ + b) * EE + h * 64;
        v = entity[base + lane] * attn_w[128 + lane]
          + entity[base + lane + 32] * attn_w[128 + lane + 32];
    }
    #pragma unroll
    for (int off = 16; off; off >>= 1) v += __shfl_down_sync(0xffffffffu, v, off);
    if (lane == 0) {
        if (which == 0)      g_dq[idx] = v;
        else if (which == 1) g_dk[idx] = v;
        else                 g_de[idx] = v;
    }
}

// ---------------- fused attention: 16 rows per block ------------------------
__global__ __launch_bounds__(256)
void attn_kernel(const float* __restrict__ attn_b)
{
    __shared__ float sT[3072];       // dk - de
    __shared__ float sqe[64];        // dq + de for the block's 2 i_src values
    __shared__ __align__(8) float sp[16][128];   // normalized probs

    const int ig  = blockIdx.x;      // 0..7 (16-row group)
    const int bh  = blockIdx.y;      // 0..23
    const int tid = threadIdx.x;
    const int g0  = bh * 16384 + ig * 2048;
    const int i_src0 = g0 / 3072;

    for (int x = tid; x < 3072; x += 256) sT[x] = g_dk[x] - g_de[x];
    if (tid < 48) {
        const int il = tid / 24, s = tid - il * 24;
        const int isrc = min(i_src0 + il, LL - 1);
        sqe[tid] = g_dq[s * 128 + isrc] + g_de[isrc * 24 + s];
    }
    __syncthreads();
    const float bias = attn_b[0];

    const int lane = tid & 31, w = tid >> 5;
    #pragma unroll
    for (int rr = 0; rr < 2; rr++) {
        const int r  = w + rr * 8;
        const int gb = g0 + r * 128;
        float sc[4];
        #pragma unroll
        for (int q = 0; q < 4; q++) {
            const int g    = gb + q * 32 + lane;
            const int isrc = g / 3072;
            const int rem  = g - isrc * 3072;
            const int s    = rem % 24;
            float v = sqe[(isrc - i_src0) * 24 + s] + sT[rem] + bias;
            sc[q] = (v >= 0.f) ? v : 0.01f * v;
        }
        float m = fmaxf(fmaxf(sc[0], sc[1]), fmaxf(sc[2], sc[3]));
        #pragma unroll
        for (int off = 16; off; off >>= 1)
            m = fmaxf(m, __shfl_xor_sync(0xffffffffu, m, off));
        float e[4], sum = 0.f;
        #pragma unroll
        for (int q = 0; q < 4; q++) { e[q] = __expf(sc[q] - m); sum += e[q]; }
        #pragma unroll
        for (int off = 16; off; off >>= 1)
            sum += __shfl_xor_sync(0xffffffffu, sum, off);
        const float inv = 1.f / sum;
        #pragma unroll
        for (int q = 0; q < 4; q++) sp[r][q * 32 + lane] = e[q] * inv;
    }
    __syncthreads();

    const int b = bh / HH, h = bh - (bh / HH) * HH;
    const int off = (h < 6) ? (2 * EH + h * 64) : (3 * EH + (h - 6) * 64);
    const int d  = tid & 63;
    const int r0 = (tid >> 6) * 4;   // 0,4,8,12
    const float* Vp = g_proj + b * 1536 + off + d;

    unsigned long long acc2[4] = {};
    #pragma unroll 4
    for (int jj = 0; jj < 128; jj += 2) {
        const float v0 = Vp[jj * 3072];
        const float v1 = Vp[(jj + 1) * 3072];
        unsigned long long vv;
        PACK2(vv, v0, v1);
        #pragma unroll
        for (int r = 0; r < 4; r++) {
            const unsigned long long pp = *(const unsigned long long*)&sp[r0 + r][jj];
            FMA2(acc2[r], pp, vv);
        }
    }
    #pragma unroll
    for (int r = 0; r < 4; r++) {
        float lo, hi;
        UNPK(lo, hi, acc2[r]);
        const int i2 = ig * 16 + r0 + r;
        g_a[(i2 * BSZ + b) * EE + h * 64 + d] = lo + hi;
    }
}

// ---------------- launcher ---------------------------------------------------
extern "C" void kernel_launch(void* const* d_in, const int* in_sizes, int n_in,
                              void* d_out, int out_size)
{
    const float* query    = (const float*)d_in[0];
    const float* entity   = (const float*)d_in[1];
    const float* conv_w   = (const float*)d_in[2];
    const float* conv_b   = (const float*)d_in[3];
    const float* q_w      = (const float*)d_in[4];
    const float* q_b      = (const float*)d_in[5];
    const float* k_w      = (const float*)d_in[6];
    const float* k_b      = (const float*)d_in[7];
    const float* v_w      = (const float*)d_in[8];
    const float* v_b      = (const float*)d_in[9];
    const float* e_w      = (const float*)d_in[10];
    const float* e_b      = (const float*)d_in[11];
    const float* attn_w   = (const float*)d_in[12];
    const float* attn_b   = (const float*)d_in[13];
    const float* deconv_w = (const float*)d_in[14];
    const float* deconv_b = (const float*)d_in[15];
    const float* out_w    = (const float*)d_in[16];
    const float* out_b    = (const float*)d_in[17];
    float* out = (float*)d_out;

    init_a_kernel<<<384, 256>>>();                 // slot 0
    init_b_kernel<<<576, 256>>>(out);              // slot 1
    gemm_kernel<0, 4><<<dim3(24, 4, 4), 256>>>(query, conv_w, nullptr, nullptr, nullptr,
                                               conv_b, nullptr, nullptr, nullptr, nullptr);  // slot 2
    gemm_kernel<1, 2><<<dim3(48, 4, 2), 256>>>(entity, q_w, k_w, v_w, e_w,
                                               q_b, k_b, v_b, e_b, nullptr);                 // slot 3 (profiled)
    dots_kernel<<<1152, 256>>>(entity, attn_w);
    attn_kernel<<<dim3(8, BHH), 256>>>(attn_b);
    gemm_kernel<2, 4><<<dim3(24, 4, 4), 256>>>(nullptr, deconv_w, nullptr, nullptr, nullptr,
                                               deconv_b, nullptr, nullptr, nullptr, nullptr);
    gemm_kernel<3, 2><<<dim3(24, 4, 2), 256>>>(nullptr, out_w, nullptr, nullptr, nullptr,
                                               out_b, nullptr, nullptr, nullptr, out);
}

// round 7
// speedup vs baseline: 1.3862x; 1.3862x over previous
#include <cuda_runtime.h>

#define LL   128
#define BSZ  2
#define EE   768
#define HH   12
#define EH   384              // E/2
#define BHH  24               // B*H

// ---------------- scratch (device globals; no allocation allowed) -----------
__device__ float g_nq[256 * EE];            // conv1d(query) output, (L,B,E)
__device__ float g_proj[256 * 4 * EH];      // [q | k | v | e] per row, (256,1536)
__device__ float g_dq[BHH * LL];
__device__ float g_dk[BHH * LL];
__device__ float g_de[LL * BHH];
__device__ float g_a[256 * EE];             // attention output in (L,B,E)
__device__ float g_y[256 * EE];             // deconv output

// ---------------- packed f32x2 helpers (attn kernel) -------------------------
#define FMA2(d, a, b) asm("fma.rn.f32x2 %0, %1, %2, %3;" \
                          : "=l"(d) : "l"(a), "l"(b), "l"(d))
#define PACK2(d, lo, hi) asm("mov.b64 %0, {%1, %2};" : "=l"(d) : "f"(lo), "f"(hi))
#define UNPK(lo, hi, s) asm("mov.b64 {%0, %1}, %2;" : "=f"(lo), "=f"(hi) : "l"(s))

// ---------------- tf32 mma.sync m16n8k8 --------------------------------------
__device__ __forceinline__ void mma8(float* d, const unsigned* a, const unsigned* b)
{
    asm volatile("mma.sync.aligned.m16n8k8.row.col.f32.tf32.tf32.f32 "
                 "{%0,%1,%2,%3}, {%4,%5,%6,%7}, {%8,%9}, {%0,%1,%2,%3};"
                 : "+f"(d[0]), "+f"(d[1]), "+f"(d[2]), "+f"(d[3])
                 : "r"(a[0]), "r"(a[1]), "r"(a[2]), "r"(a[3]),
                   "r"(b[0]), "r"(b[1]));
}

// ---------------- init: zero atomic-accumulation targets ---------------------
__global__ __launch_bounds__(256)
void init_a_kernel()
{
    const int idx = blockIdx.x * 256 + threadIdx.x;   // 98304 float4
    float4 z = {0.f, 0.f, 0.f, 0.f};
    if (idx < 49152) ((float4*)g_nq)[idx] = z;
    else             ((float4*)g_y)[idx - 49152] = z;
}
__global__ __launch_bounds__(256)
void init_b_kernel(float* __restrict__ out)
{
    const int idx = blockIdx.x * 256 + threadIdx.x;   // 49152 float4
    float4 z = {0.f, 0.f, 0.f, 0.f};
    ((float4*)out)[idx] = z;
}

// ---------------- tensor-core GEMM, tile 64x64, BK=32, 8 warps ---------------
// warp (wm = wid>>2, wn = wid&3): 32x16 sub-tile, 2x2 m16n8 mma fragments.
// 3-term tf32 split for fp32-grade accuracy.
// MODE 0: nq   = conv(query)      M=256 N=768  K=1536  KSPLIT=2 (atomic)
// MODE 1: proj = [q|k|v|e]        M=256 N=1536 K=768   KSPLIT=1 (store)
// MODE 2: y    = deconv(a)        M=256 N=768  K=1536  KSPLIT=2 (atomic)
// MODE 3: out  = y @ out_w^T      M=256 N=768  K=768   KSPLIT=2 (atomic)
template<int MODE, int KSPLIT>
__global__ __launch_bounds__(256)
void gemm_kernel(const float* __restrict__ A0,
                 const float* __restrict__ W0,
                 const float* __restrict__ W1,
                 const float* __restrict__ W2,
                 const float* __restrict__ W3,
                 const float* __restrict__ bb0,
                 const float* __restrict__ bb1,
                 const float* __restrict__ bb2,
                 const float* __restrict__ bb3,
                 float* __restrict__ Cout)
{
    constexpr int BM = 64, BN = 64, BK = 32;
    constexpr int N  = (MODE == 1) ? 1536 : 768;
    constexpr int K  = (MODE == 0 || MODE == 2) ? 1536 : 768;
    constexpr int NT = K / KSPLIT / BK;
    constexpr int ASTR = 72;   // (8k+r) mod 32 distinct -> conflict-free frags
    constexpr int BSTR = 72;

    __shared__ __align__(16) float As[2][BK][ASTR];
    __shared__ __align__(16) float Bs[2][BK][BSTR];

    const int bn   = blockIdx.x * BN;
    const int bm   = blockIdx.y * BM;
    const int koff = blockIdx.z * (K / KSPLIT);
    const int tid  = threadIdx.x;
    const int lane = tid & 31;
    const int wid  = tid >> 5;
    const int wm   = wid >> 2;          // 0..1 -> rows wm*32
    const int wn   = wid & 3;           // 0..3 -> cols wn*16
    const int grp  = lane >> 2;         // 0..7
    const int thr4 = lane & 3;          // 0..3

    // loader coordinates (256 threads fill 64x32 A and 32x64 B)
    const int aKK = tid & 31;            // A: k within tile
    const int aTY = tid >> 5;            // A: row fragment 0..7
    const int bKK = tid & 31;            // B: k (loads a column of W row o)
    const int bTY = tid >> 5;            // o fragment 0..7
    const int bO2 = tid & 63;            // B (mode 2): o
    const int bK2 = tid >> 6;            // k fragment 0..3

    float ar[8], br[8];

    auto loadA = [&](int t) {
        const int k = koff + t * BK + aKK;
        #pragma unroll
        for (int i = 0; i < 8; i++) {
            const int row = bm + i * 8 + aTY;
            float v;
            if (MODE == 0) {
                if (k < EE) v = (row >= BSZ) ? A0[(row - BSZ) * EE + k] : 0.f;
                else        v = A0[row * EE + (k - EE)];
            } else if (MODE == 1) {
                const float* Ap = (bn >= 3 * EH) ? A0 : g_nq;
                v = Ap[row * EE + k];
            } else if (MODE == 2) {
                if (k < EE) v = g_a[row * EE + k];
                else        v = (row >= BSZ) ? g_a[(row - BSZ) * EE + (k - EE)] : 0.f;
            } else {
                v = g_y[row * EE + k];
            }
            ar[i] = v;
        }
    };

    auto loadB = [&](int t) {
        if (MODE == 2) {
            const int o = bn + bO2;
            #pragma unroll
            for (int i = 0; i < 8; i++) {
                const int k = koff + t * BK + i * 4 + bK2;
                br[i] = (k < EE) ? W0[(k * EE + o) * 2]
                                 : W0[((k - EE) * EE + o) * 2 + 1];
            }
        } else {
            const int k = koff + t * BK + bKK;
            #pragma unroll
            for (int i = 0; i < 8; i++) {
                const int o = bn + i * 8 + bTY;
                float v;
                if (MODE == 0) {
                    v = (k < EE) ? W0[(o * EE + k) * 2]
                                 : W0[(o * EE + (k - EE)) * 2 + 1];
                } else if (MODE == 1) {
                    if (o < EH)          v = W0[o * EE + k];
                    else if (o < 2 * EH) v = W1[(o - EH) * EE + k];
                    else if (o < 3 * EH) v = W2[(o - 2 * EH) * EE + k];
                    else                 v = W3[(o - 3 * EH) * EE + k];
                } else {
                    v = W0[o * EE + k];
                }
                br[i] = v;
            }
        }
    };

    auto storeTiles = [&](int nb) {
        #pragma unroll
        for (int i = 0; i < 8; i++) As[nb][aKK][i * 8 + aTY] = ar[i];
        if (MODE == 2) {
            #pragma unroll
            for (int i = 0; i < 8; i++) Bs[nb][i * 4 + bK2][bO2] = br[i];
        } else {
            #pragma unroll
            for (int i = 0; i < 8; i++) Bs[nb][bKK][i * 8 + bTY] = br[i];
        }
    };

    float dm[2][2][4] = {};   // hi*hi accumulators
    float dc[2][2][4] = {};   // hi*lo + lo*hi correction accumulators

    loadA(0); loadB(0);
    storeTiles(0);
    __syncthreads();

    int buf = 0;
    for (int t = 0; t < NT; t++) {
        if (t + 1 < NT) { loadA(t + 1); loadB(t + 1); }

        #pragma unroll
        for (int k8 = 0; k8 < BK / 8; k8++) {
            const int k0 = k8 * 8;
            // ---- A fragments: af[mt][0..3] ----
            unsigned ah[2][4], al[2][4];
            #pragma unroll
            for (int mt = 0; mt < 2; mt++) {
                const int rb = wm * 32 + mt * 16 + grp;
                float f0 = As[buf][k0 + thr4][rb];
                float f1 = As[buf][k0 + thr4][rb + 8];
                float f2 = As[buf][k0 + 4 + thr4][rb];
                float f3 = As[buf][k0 + 4 + thr4][rb + 8];
                float fv[4] = {f0, f1, f2, f3};
                #pragma unroll
                for (int r = 0; r < 4; r++) {
                    unsigned hb = __float_as_uint(fv[r]) & 0xffffe000u;
                    ah[mt][r] = hb;
                    al[mt][r] = __float_as_uint(fv[r] - __uint_as_float(hb));
                }
            }
            // ---- B fragments: bf[nt][0..1] ----
            unsigned bh[2][2], bl[2][2];
            #pragma unroll
            for (int nt = 0; nt < 2; nt++) {
                const int cb = wn * 16 + nt * 8 + grp;
                float f0 = Bs[buf][k0 + thr4][cb];
                float f1 = Bs[buf][k0 + 4 + thr4][cb];
                unsigned h0 = __float_as_uint(f0) & 0xffffe000u;
                unsigned h1 = __float_as_uint(f1) & 0xffffe000u;
                bh[nt][0] = h0; bh[nt][1] = h1;
                bl[nt][0] = __float_as_uint(f0 - __uint_as_float(h0));
                bl[nt][1] = __float_as_uint(f1 - __uint_as_float(h1));
            }
            // ---- 12 mma ----
            #pragma unroll
            for (int mt = 0; mt < 2; mt++)
                #pragma unroll
                for (int nt = 0; nt < 2; nt++) {
                    mma8(dm[mt][nt], ah[mt], bh[nt]);
                    mma8(dc[mt][nt], ah[mt], bl[nt]);
                    mma8(dc[mt][nt], al[mt], bh[nt]);
                }
        }

        if (t + 1 < NT) {
            storeTiles(buf ^ 1);
            __syncthreads();
            buf ^= 1;
        }
    }

    // ---- epilogue -------------------------------------------------------------
    float* C = (MODE == 0) ? g_nq : (MODE == 1) ? g_proj
             : (MODE == 2) ? g_y  : Cout;

    #pragma unroll
    for (int nt = 0; nt < 2; nt++) {
        const int col = bn + wn * 16 + nt * 8 + 2 * thr4;
        float bias0, bias1;
        if (MODE == 1) {
            const int seg = col / EH;                  // EH not pow2: no masking
            const float* bp = (seg == 0) ? bb0 : (seg == 1) ? bb1
                            : (seg == 2) ? bb2 : bb3;
            const int ob = col - seg * EH;
            bias0 = bp[ob]; bias1 = bp[ob + 1];
        } else {
            bias0 = bb0[col]; bias1 = bb0[col + 1];
        }
        if (KSPLIT == 2 && blockIdx.z != 0) { bias0 = 0.f; bias1 = 0.f; }

        #pragma unroll
        for (int mt = 0; mt < 2; mt++) {
            const int row = bm + wm * 32 + mt * 16 + grp;
            float v00 = dm[mt][nt][0] + dc[mt][nt][0] + bias0;
            float v01 = dm[mt][nt][1] + dc[mt][nt][1] + bias1;
            float v10 = dm[mt][nt][2] + dc[mt][nt][2] + bias0;
            float v11 = dm[mt][nt][3] + dc[mt][nt][3] + bias1;
            if (KSPLIT == 1) {
                float2 p0 = {v00, v01};
                float2 p1 = {v10, v11};
                *(float2*)&C[row * N + col]       = p0;
                *(float2*)&C[(row + 8) * N + col] = p1;
            } else {
                atomicAdd(&C[row * N + col],           v00);
                atomicAdd(&C[row * N + col + 1],       v01);
                atomicAdd(&C[(row + 8) * N + col],     v10);
                atomicAdd(&C[(row + 8) * N + col + 1], v11);
            }
        }
    }
}

// ---------------- dq / dk / de precompute (9216 length-64 dots) -------------
__global__ __launch_bounds__(256)
void dots_kernel(const float* __restrict__ entity,
                 const float* __restrict__ attn_w)
{
    int w    = (blockIdx.x * blockDim.x + threadIdx.x) >> 5;
    int lane = threadIdx.x & 31;
    if (w >= 3 * BHH * LL) return;
    int which = w / (BHH * LL);
    int idx   = w % (BHH * LL);
    float v;
    if (which < 2) {
        int m = idx >> 7, x = idx & 127;
        int b = m / HH, h = m % HH;
        int row = x * BSZ + b;
        int base = (h < 6) ? (row * 1536 + which * EH + h * 64)
                           : (row * 1536 + 3 * EH + (h - 6) * 64);
        const float* wv = attn_w + which * 64;
        v = g_proj[base + lane] * wv[lane] + g_proj[base + lane + 32] * wv[lane + 32];
    } else {
        int i = idx / BHH, s = idx % BHH;
        int b = s / HH, h = s % HH;
        int base = (i * BSZ + b) * EE + h * 64;
        v = entity[base + lane] * attn_w[128 + lane]
          + entity[base + lane + 32] * attn_w[128 + lane + 32];
    }
    #pragma unroll
    for (int off = 16; off; off >>= 1) v += __shfl_down_sync(0xffffffffu, v, off);
    if (lane == 0) {
        if (which == 0)      g_dq[idx] = v;
        else if (which == 1) g_dk[idx] = v;
        else                 g_de[idx] = v;
    }
}

// ---------------- fused attention: 16 rows per block ------------------------
__global__ __launch_bounds__(256)
void attn_kernel(const float* __restrict__ attn_b)
{
    __shared__ float sT[3072];       // dk - de
    __shared__ float sqe[64];        // dq + de for the block's 2 i_src values
    __shared__ __align__(8) float sp[16][128];   // normalized probs

    const int ig  = blockIdx.x;      // 0..7 (16-row group)
    const int bh  = blockIdx.y;      // 0..23
    const int tid = threadIdx.x;
    const int g0  = bh * 16384 + ig * 2048;
    const int i_src0 = g0 / 3072;

    for (int x = tid; x < 3072; x += 256) sT[x] = g_dk[x] - g_de[x];
    if (tid < 48) {
        const int il = tid / 24, s = tid - il * 24;
        const int isrc = min(i_src0 + il, LL - 1);
        sqe[tid] = g_dq[s * 128 + isrc] + g_de[isrc * 24 + s];
    }
    __syncthreads();
    const float bias = attn_b[0];

    const int lane = tid & 31, w = tid >> 5;
    #pragma unroll
    for (int rr = 0; rr < 2; rr++) {
        const int r  = w + rr * 8;
        const int gb = g0 + r * 128;
        float sc[4];
        #pragma unroll
        for (int q = 0; q < 4; q++) {
            const int g    = gb + q * 32 + lane;
            const int isrc = g / 3072;
            const int rem  = g - isrc * 3072;
            const int s    = rem % 24;
            float v = sqe[(isrc - i_src0) * 24 + s] + sT[rem] + bias;
            sc[q] = (v >= 0.f) ? v : 0.01f * v;
        }
        float m = fmaxf(fmaxf(sc[0], sc[1]), fmaxf(sc[2], sc[3]));
        #pragma unroll
        for (int off = 16; off; off >>= 1)
            m = fmaxf(m, __shfl_xor_sync(0xffffffffu, m, off));
        float e[4], sum = 0.f;
        #pragma unroll
        for (int q = 0; q < 4; q++) { e[q] = __expf(sc[q] - m); sum += e[q]; }
        #pragma unroll
        for (int off = 16; off; off >>= 1)
            sum += __shfl_xor_sync(0xffffffffu, sum, off);
        const float inv = 1.f / sum;
        #pragma unroll
        for (int q = 0; q < 4; q++) sp[r][q * 32 + lane] = e[q] * inv;
    }
    __syncthreads();

    const int b = bh / HH, h = bh - (bh / HH) * HH;
    const int off = (h < 6) ? (2 * EH + h * 64) : (3 * EH + (h - 6) * 64);
    const int d  = tid & 63;
    const int r0 = (tid >> 6) * 4;   // 0,4,8,12
    const float* Vp = g_proj + b * 1536 + off + d;

    unsigned long long acc2[4] = {};
    #pragma unroll 4
    for (int jj = 0; jj < 128; jj += 2) {
        const float v0 = Vp[jj * 3072];
        const float v1 = Vp[(jj + 1) * 3072];
        unsigned long long vv;
        PACK2(vv, v0, v1);
        #pragma unroll
        for (int r = 0; r < 4; r++) {
            const unsigned long long pp = *(const unsigned long long*)&sp[r0 + r][jj];
            FMA2(acc2[r], pp, vv);
        }
    }
    #pragma unroll
    for (int r = 0; r < 4; r++) {
        float lo, hi;
        UNPK(lo, hi, acc2[r]);
        const int i2 = ig * 16 + r0 + r;
        g_a[(i2 * BSZ + b) * EE + h * 64 + d] = lo + hi;
    }
}

// ---------------- launcher ---------------------------------------------------
extern "C" void kernel_launch(void* const* d_in, const int* in_sizes, int n_in,
                              void* d_out, int out_size)
{
    const float* query    = (const float*)d_in[0];
    const float* entity   = (const float*)d_in[1];
    const float* conv_w   = (const float*)d_in[2];
    const float* conv_b   = (const float*)d_in[3];
    const float* q_w      = (const float*)d_in[4];
    const float* q_b      = (const float*)d_in[5];
    const float* k_w      = (const float*)d_in[6];
    const float* k_b      = (const float*)d_in[7];
    const float* v_w      = (const float*)d_in[8];
    const float* v_b      = (const float*)d_in[9];
    const float* e_w      = (const float*)d_in[10];
    const float* e_b      = (const float*)d_in[11];
    const float* attn_w   = (const float*)d_in[12];
    const float* attn_b   = (const float*)d_in[13];
    const float* deconv_w = (const float*)d_in[14];
    const float* deconv_b = (const float*)d_in[15];
    const float* out_w    = (const float*)d_in[16];
    const float* out_b    = (const float*)d_in[17];
    float* out = (float*)d_out;

    init_a_kernel<<<384, 256>>>();                 // slot 0
    init_b_kernel<<<192, 256>>>(out);              // slot 1
    gemm_kernel<0, 2><<<dim3(12, 4, 2), 256>>>(query, conv_w, nullptr, nullptr, nullptr,
                                               conv_b, nullptr, nullptr, nullptr, nullptr);  // slot 2
    gemm_kernel<1, 1><<<dim3(24, 4, 1), 256>>>(entity, q_w, k_w, v_w, e_w,
                                               q_b, k_b, v_b, e_b, nullptr);                 // slot 3 (profiled)
    dots_kernel<<<1152, 256>>>(entity, attn_w);
    attn_kernel<<<dim3(8, BHH), 256>>>(attn_b);
    gemm_kernel<2, 2><<<dim3(12, 4, 2), 256>>>(nullptr, deconv_w, nullptr, nullptr, nullptr,
                                               deconv_b, nullptr, nullptr, nullptr, nullptr);
    gemm_kernel<3, 2><<<dim3(12, 4, 2), 256>>>(nullptr, out_w, nullptr, nullptr, nullptr,
                                               out_b, nullptr, nullptr, nullptr, out);
}

// round 8
// speedup vs baseline: 2.0199x; 1.4571x over previous
#include <cuda_runtime.h>

#define LL   128
#define BSZ  2
#define EE   768
#define HH   12
#define EH   384              // E/2
#define BHH  24               // B*H

// ---------------- scratch (device globals; no allocation allowed) -----------
__device__ float g_nq[256 * EE];            // conv1d(query) output, (L,B,E)
__device__ float g_proj[256 * 4 * EH];      // [q | k | v | e] per row, (256,1536)
__device__ float g_dq[BHH * LL];
__device__ float g_dk[BHH * LL];
__device__ float g_de[LL * BHH];
__device__ float g_a[256 * EE];             // attention output in (L,B,E)
__device__ float g_y[256 * EE];             // deconv output

// ---------------- packed f32x2 helpers (attn kernel) -------------------------
#define FMA2(d, a, b) asm("fma.rn.f32x2 %0, %1, %2, %3;" \
                          : "=l"(d) : "l"(a), "l"(b), "l"(d))
#define PACK2(d, lo, hi) asm("mov.b64 %0, {%1, %2};" : "=l"(d) : "f"(lo), "f"(hi))
#define UNPK(lo, hi, s) asm("mov.b64 {%0, %1}, %2;" : "=f"(lo), "=f"(hi) : "l"(s))

// ---------------- tf32 mma.sync m16n8k8 --------------------------------------
__device__ __forceinline__ void mma8(float* d, const unsigned* a, const unsigned* b)
{
    asm volatile("mma.sync.aligned.m16n8k8.row.col.f32.tf32.tf32.f32 "
                 "{%0,%1,%2,%3}, {%4,%5,%6,%7}, {%8,%9}, {%0,%1,%2,%3};"
                 : "+f"(d[0]), "+f"(d[1]), "+f"(d[2]), "+f"(d[3])
                 : "r"(a[0]), "r"(a[1]), "r"(a[2]), "r"(a[3]),
                   "r"(b[0]), "r"(b[1]));
}

// ---------------- init: zero atomic-accumulation targets ---------------------
__global__ __launch_bounds__(256)
void init_a_kernel()
{
    const int idx = blockIdx.x * 256 + threadIdx.x;   // 98304 float4
    float4 z = {0.f, 0.f, 0.f, 0.f};
    if (idx < 49152) ((float4*)g_nq)[idx] = z;
    else             ((float4*)g_y)[idx - 49152] = z;
}
__global__ __launch_bounds__(256)
void init_b_kernel(float* __restrict__ out)
{
    const int idx = blockIdx.x * 256 + threadIdx.x;   // 147456 float4
    float4 z = {0.f, 0.f, 0.f, 0.f};
    if (idx < 49152) ((float4*)out)[idx] = z;
    else             ((float4*)g_proj)[idx - 49152] = z;
}

// ---------------- tensor-core GEMM, tile 32x64, BK=32, 4 warps ---------------
// warp (wm = wid&1, wn = wid>>1): 16x32 sub-tile = 4 m16n8 frags along n.
// smem layout [row][k], stride 36: frag reads AND loader stores conflict-free.
// 3-term tf32 split for fp32-grade accuracy. All outputs accumulated atomically.
// MODE 0: nq   = conv(query)      M=256 N=768  K=1536  KSPLIT=4
// MODE 1: proj = [q|k|v|e]        M=256 N=1536 K=768   KSPLIT=2
// MODE 2: y    = deconv(a)        M=256 N=768  K=1536  KSPLIT=4
// MODE 3: out  = y @ out_w^T      M=256 N=768  K=768   KSPLIT=2
template<int MODE, int KSPLIT>
__global__ __launch_bounds__(128)
void gemm_kernel(const float* __restrict__ A0,
                 const float* __restrict__ W0,
                 const float* __restrict__ W1,
                 const float* __restrict__ W2,
                 const float* __restrict__ W3,
                 const float* __restrict__ bb0,
                 const float* __restrict__ bb1,
                 const float* __restrict__ bb2,
                 const float* __restrict__ bb3,
                 float* __restrict__ Cout)
{
    constexpr int BM = 32, BN = 64, BK = 32;
    constexpr int N  = (MODE == 1) ? 1536 : 768;
    constexpr int K  = (MODE == 0 || MODE == 2) ? 1536 : 768;
    constexpr int NT = K / KSPLIT / BK;
    constexpr int STR = 36;    // [row][k] stride: frag bank = 4*grp+thr4, distinct

    __shared__ __align__(16) float As[2][BM][STR];
    __shared__ __align__(16) float Bs[2][BN][STR];

    const int bn   = blockIdx.x * BN;
    const int bm   = blockIdx.y * BM;
    const int koff = blockIdx.z * (K / KSPLIT);
    const int tid  = threadIdx.x;
    const int lane = tid & 31;
    const int wid  = tid >> 5;            // 0..3
    const int rb   = (wid & 1) * 16;      // warp row base
    const int cbB  = (wid >> 1) * 32;     // warp col base
    const int grp  = lane >> 2;           // 0..7
    const int thr4 = lane & 3;            // 0..3

    // loader coordinates
    const int aKK = tid & 31;             // A/B (modes 0,1,3): local k
    const int aTY = tid >> 5;             // fragment index 0..3
    const int bO2 = tid & 63;             // B (mode 2): local o
    const int bK2 = tid >> 6;             // k sub 0..1

    float ar[8], br[16];

    auto loadA = [&](int t) {
        const int k = koff + t * BK + aKK;
        #pragma unroll
        for (int i = 0; i < 8; i++) {
            const int row = bm + i * 4 + aTY;
            float v;
            if (MODE == 0) {
                if (k < EE) v = (row >= BSZ) ? A0[(row - BSZ) * EE + k] : 0.f;
                else        v = A0[row * EE + (k - EE)];
            } else if (MODE == 1) {
                const float* Ap = (bn >= 3 * EH) ? A0 : g_nq;
                v = Ap[row * EE + k];
            } else if (MODE == 2) {
                if (k < EE) v = g_a[row * EE + k];
                else        v = (row >= BSZ) ? g_a[(row - BSZ) * EE + (k - EE)] : 0.f;
            } else {
                v = g_y[row * EE + k];
            }
            ar[i] = v;
        }
    };

    auto loadB = [&](int t) {
        if (MODE == 2) {
            const int o = bn + bO2;
            #pragma unroll
            for (int i = 0; i < 16; i++) {
                const int k = koff + t * BK + i * 2 + bK2;
                br[i] = (k < EE) ? W0[(k * EE + o) * 2]
                                 : W0[((k - EE) * EE + o) * 2 + 1];
            }
        } else {
            const int k = koff + t * BK + aKK;
            #pragma unroll
            for (int i = 0; i < 16; i++) {
                const int o = bn + i * 4 + aTY;
                float v;
                if (MODE == 0) {
                    v = (k < EE) ? W0[(o * EE + k) * 2]
                                 : W0[(o * EE + (k - EE)) * 2 + 1];
                } else if (MODE == 1) {
                    if (o < EH)          v = W0[o * EE + k];
                    else if (o < 2 * EH) v = W1[(o - EH) * EE + k];
                    else if (o < 3 * EH) v = W2[(o - 2 * EH) * EE + k];
                    else                 v = W3[(o - 3 * EH) * EE + k];
                } else {
                    v = W0[o * EE + k];
                }
                br[i] = v;
            }
        }
    };

    auto storeTiles = [&](int nb) {
        #pragma unroll
        for (int i = 0; i < 8; i++) As[nb][i * 4 + aTY][aKK] = ar[i];
        if (MODE == 2) {
            #pragma unroll
            for (int i = 0; i < 16; i++) Bs[nb][bO2][i * 2 + bK2] = br[i];
        } else {
            #pragma unroll
            for (int i = 0; i < 16; i++) Bs[nb][i * 4 + aTY][aKK] = br[i];
        }
    };

    float dm[4][4] = {};   // hi*hi accumulators (per n-tile)
    float dc[4][4] = {};   // hi*lo + lo*hi corrections

    loadA(0); loadB(0);
    storeTiles(0);
    __syncthreads();

    int buf = 0;
    for (int t = 0; t < NT; t++) {
        if (t + 1 < NT) { loadA(t + 1); loadB(t + 1); }

        #pragma unroll
        for (int k8 = 0; k8 < BK / 8; k8++) {
            const int k0 = k8 * 8;
            // ---- A fragment (m16k8) ----
            float fv[4];
            fv[0] = As[buf][rb + grp][k0 + thr4];
            fv[1] = As[buf][rb + grp + 8][k0 + thr4];
            fv[2] = As[buf][rb + grp][k0 + thr4 + 4];
            fv[3] = As[buf][rb + grp + 8][k0 + thr4 + 4];
            unsigned ah[4], al[4];
            #pragma unroll
            for (int r = 0; r < 4; r++) {
                unsigned hb = __float_as_uint(fv[r]) & 0xffffe000u;
                ah[r] = hb;
                al[r] = __float_as_uint(fv[r] - __uint_as_float(hb));
            }
            // ---- 4 B fragments (k8n8) + 12 mma ----
            #pragma unroll
            for (int nt = 0; nt < 4; nt++) {
                const int cb = cbB + nt * 8 + grp;
                float g0 = Bs[buf][cb][k0 + thr4];
                float g1 = Bs[buf][cb][k0 + thr4 + 4];
                unsigned h0 = __float_as_uint(g0) & 0xffffe000u;
                unsigned h1 = __float_as_uint(g1) & 0xffffe000u;
                unsigned bh[2] = {h0, h1};
                unsigned bl[2] = {__float_as_uint(g0 - __uint_as_float(h0)),
                                  __float_as_uint(g1 - __uint_as_float(h1))};
                mma8(dm[nt], ah, bh);
                mma8(dc[nt], ah, bl);
                mma8(dc[nt], al, bh);
            }
        }

        if (t + 1 < NT) {
            storeTiles(buf ^ 1);
            __syncthreads();
            buf ^= 1;
        }
    }

    // ---- epilogue: atomic accumulate (+bias on z==0) ----------------------------
    float* C = (MODE == 0) ? g_nq : (MODE == 1) ? g_proj
             : (MODE == 2) ? g_y  : Cout;

    #pragma unroll
    for (int nt = 0; nt < 4; nt++) {
        const int col = bn + cbB + nt * 8 + 2 * thr4;
        float bias0, bias1;
        if (MODE == 1) {
            const int seg = col / EH;                  // EH not pow2: no masking
            const float* bp = (seg == 0) ? bb0 : (seg == 1) ? bb1
                            : (seg == 2) ? bb2 : bb3;
            const int ob = col - seg * EH;
            bias0 = bp[ob]; bias1 = bp[ob + 1];
        } else {
            bias0 = bb0[col]; bias1 = bb0[col + 1];
        }
        if (blockIdx.z != 0) { bias0 = 0.f; bias1 = 0.f; }

        const int row = bm + rb + grp;
        atomicAdd(&C[row * N + col],           dm[nt][0] + dc[nt][0] + bias0);
        atomicAdd(&C[row * N + col + 1],       dm[nt][1] + dc[nt][1] + bias1);
        atomicAdd(&C[(row + 8) * N + col],     dm[nt][2] + dc[nt][2] + bias0);
        atomicAdd(&C[(row + 8) * N + col + 1], dm[nt][3] + dc[nt][3] + bias1);
    }
}

// ---------------- dq / dk / de precompute (9216 length-64 dots) -------------
__global__ __launch_bounds__(256)
void dots_kernel(const float* __restrict__ entity,
                 const float* __restrict__ attn_w)
{
    int w    = (blockIdx.x * blockDim.x + threadIdx.x) >> 5;
    int lane = threadIdx.x & 31;
    if (w >= 3 * BHH * LL) return;
    int which = w / (BHH * LL);
    int idx   = w % (BHH * LL);
    float v;
    if (which < 2) {
        int m = idx >> 7, x = idx & 127;
        int b = m / HH, h = m % HH;
        int row = x * BSZ + b;
        int base = (h < 6) ? (row * 1536 + which * EH + h * 64)
                           : (row * 1536 + 3 * EH + (h - 6) * 64);
        const float* wv = attn_w + which * 64;
        v = g_proj[base + lane] * wv[lane] + g_proj[base + lane + 32] * wv[lane + 32];
    } else {
        int i = idx / BHH, s = idx % BHH;
        int b = s / HH, h = s % HH;
        int base = (i * BSZ + b) * EE + h * 64;
        v = entity[base + lane] * attn_w[128 + lane]
          + entity[base + lane + 32] * attn_w[128 + lane + 32];
    }
    #pragma unroll
    for (int off = 16; off; off >>= 1) v += __shfl_down_sync(0xffffffffu, v, off);
    if (lane == 0) {
        if (which == 0)      g_dq[idx] = v;
        else if (which == 1) g_dk[idx] = v;
        else                 g_de[idx] = v;
    }
}

// ---------------- fused attention: 16 rows per block ------------------------
__global__ __launch_bounds__(256)
void attn_kernel(const float* __restrict__ attn_b)
{
    __shared__ float sT[3072];       // dk - de
    __shared__ float sqe[64];        // dq + de for the block's 2 i_src values
    __shared__ __align__(8) float sp[16][128];   // normalized probs

    const int ig  = blockIdx.x;      // 0..7 (16-row group)
    const int bh  = blockIdx.y;      // 0..23
    const int tid = threadIdx.x;
    const int g0  = bh * 16384 + ig * 2048;
    const int i_src0 = g0 / 3072;

    for (int x = tid; x < 3072; x += 256) sT[x] = g_dk[x] - g_de[x];
    if (tid < 48) {
        const int il = tid / 24, s = tid - il * 24;
        const int isrc = min(i_src0 + il, LL - 1);
        sqe[tid] = g_dq[s * 128 + isrc] + g_de[isrc * 24 + s];
    }
    __syncthreads();
    const float bias = attn_b[0];

    const int lane = tid & 31, w = tid >> 5;
    #pragma unroll
    for (int rr = 0; rr < 2; rr++) {
        const int r  = w + rr * 8;
        const int gb = g0 + r * 128;
        float sc[4];
        #pragma unroll
        for (int q = 0; q < 4; q++) {
            const int g    = gb + q * 32 + lane;
            const int isrc = g / 3072;
            const int rem  = g - isrc * 3072;
            const int s    = rem % 24;
            float v = sqe[(isrc - i_src0) * 24 + s] + sT[rem] + bias;
            sc[q] = (v >= 0.f) ? v : 0.01f * v;
        }
        float m = fmaxf(fmaxf(sc[0], sc[1]), fmaxf(sc[2], sc[3]));
        #pragma unroll
        for (int off = 16; off; off >>= 1)
            m = fmaxf(m, __shfl_xor_sync(0xffffffffu, m, off));
        float e[4], sum = 0.f;
        #pragma unroll
        for (int q = 0; q < 4; q++) { e[q] = __expf(sc[q] - m); sum += e[q]; }
        #pragma unroll
        for (int off = 16; off; off >>= 1)
            sum += __shfl_xor_sync(0xffffffffu, sum, off);
        const float inv = 1.f / sum;
        #pragma unroll
        for (int q = 0; q < 4; q++) sp[r][q * 32 + lane] = e[q] * inv;
    }
    __syncthreads();

    const int b = bh / HH, h = bh - (bh / HH) * HH;
    const int off = (h < 6) ? (2 * EH + h * 64) : (3 * EH + (h - 6) * 64);
    const int d  = tid & 63;
    const int r0 = (tid >> 6) * 4;   // 0,4,8,12
    const float* Vp = g_proj + b * 1536 + off + d;

    unsigned long long acc2[4] = {};
    #pragma unroll 4
    for (int jj = 0; jj < 128; jj += 2) {
        const float v0 = Vp[jj * 3072];
        const float v1 = Vp[(jj + 1) * 3072];
        unsigned long long vv;
        PACK2(vv, v0, v1);
        #pragma unroll
        for (int r = 0; r < 4; r++) {
            const unsigned long long pp = *(const unsigned long long*)&sp[r0 + r][jj];
            FMA2(acc2[r], pp, vv);
        }
    }
    #pragma unroll
    for (int r = 0; r < 4; r++) {
        float lo, hi;
        UNPK(lo, hi, acc2[r]);
        const int i2 = ig * 16 + r0 + r;
        g_a[(i2 * BSZ + b) * EE + h * 64 + d] = lo + hi;
    }
}

// ---------------- launcher ---------------------------------------------------
extern "C" void kernel_launch(void* const* d_in, const int* in_sizes, int n_in,
                              void* d_out, int out_size)
{
    const float* query    = (const float*)d_in[0];
    const float* entity   = (const float*)d_in[1];
    const float* conv_w   = (const float*)d_in[2];
    const float* conv_b   = (const float*)d_in[3];
    const float* q_w      = (const float*)d_in[4];
    const float* q_b      = (const float*)d_in[5];
    const float* k_w      = (const float*)d_in[6];
    const float* k_b      = (const float*)d_in[7];
    const float* v_w      = (const float*)d_in[8];
    const float* v_b      = (const float*)d_in[9];
    const float* e_w      = (const float*)d_in[10];
    const float* e_b      = (const float*)d_in[11];
    const float* attn_w   = (const float*)d_in[12];
    const float* attn_b   = (const float*)d_in[13];
    const float* deconv_w = (const float*)d_in[14];
    const float* deconv_b = (const float*)d_in[15];
    const float* out_w    = (const float*)d_in[16];
    const float* out_b    = (const float*)d_in[17];
    float* out = (float*)d_out;

    init_a_kernel<<<384, 256>>>();                 // slot 0
    init_b_kernel<<<576, 256>>>(out);              // slot 1
    gemm_kernel<0, 4><<<dim3(12, 8, 4), 128>>>(query, conv_w, nullptr, nullptr, nullptr,
                                               conv_b, nullptr, nullptr, nullptr, nullptr);  // slot 2
    gemm_kernel<1, 2><<<dim3(24, 8, 2), 128>>>(entity, q_w, k_w, v_w, e_w,
                                               q_b, k_b, v_b, e_b, nullptr);                 // slot 3 (profiled)
    dots_kernel<<<1152, 256>>>(entity, attn_w);
    attn_kernel<<<dim3(8, BHH), 256>>>(attn_b);
    gemm_kernel<2, 4><<<dim3(12, 8, 4), 128>>>(nullptr, deconv_w, nullptr, nullptr, nullptr,
                                               deconv_b, nullptr, nullptr, nullptr, nullptr);
    gemm_kernel<3, 2><<<dim3(12, 8, 2), 128>>>(nullptr, out_w, nullptr, nullptr, nullptr,
                                               out_b, nullptr, nullptr, nullptr, out);
}